// round 4
// baseline (speedup 1.0000x reference)
#include <cuda_runtime.h>
#include <cuda_bf16.h>

#define N_NODES 50000
#define E_EDGES 800000
#define D 64
#define NC 40

// Scratch (allocation-free rule: __device__ globals). 16B-aligned for float4 access.
__device__ __align__(16) float g_dinv[N_NODES];      // deg, then rsqrt(deg) in place
__device__ __align__(16) float g_hs [N_NODES * D];   // pre-scaled transformed features
__device__ __align__(16) float g_agg[N_NODES * D];   // aggregation target

// ---------------------------------------------------------------------------
// Degree: deg[i] = 1 (self-loop) + #edges with dst==i ; then dinv = rsqrt(deg)
// ---------------------------------------------------------------------------
__global__ void k_init_deg() {
    int i = blockIdx.x * blockDim.x + threadIdx.x;
    if (i < N_NODES) g_dinv[i] = 1.0f;
}

__global__ void k_count_deg(const int* __restrict__ dst) {
    int e = blockIdx.x * blockDim.x + threadIdx.x;
    if (e < E_EDGES) atomicAdd(&g_dinv[dst[e]], 1.0f);
}

__global__ void k_finish_dinv() {
    int i = blockIdx.x * blockDim.x + threadIdx.x;
    if (i < N_NODES) g_dinv[i] = rsqrtf(g_dinv[i]);
}

// ---------------------------------------------------------------------------
// Layer-1 GEMM: hs = (x @ W1) * dinv[row]; agg = hs  (self-loop term)
// 256 threads = 4 rows x 64 cols per block
// ---------------------------------------------------------------------------
__global__ void k_gemm1(const float* __restrict__ x, const float* __restrict__ W1) {
    __shared__ float sW[D * D];
    __shared__ float sx[4][D];
    int tid = threadIdx.x;
    #pragma unroll
    for (int i = tid; i < D * D; i += 256) sW[i] = W1[i];
    int r = tid >> 6, c = tid & 63;
    int row = blockIdx.x * 4 + r;
    sx[r][c] = x[row * D + c];
    __syncthreads();
    float acc = 0.0f;
    #pragma unroll
    for (int k = 0; k < D; k++) acc = fmaf(sx[r][k], sW[k * D + c], acc);
    float v = acc * g_dinv[row];
    g_hs [row * D + c] = v;
    g_agg[row * D + c] = v;
}

// ---------------------------------------------------------------------------
// Edge scatter: agg[dst] += hs[src]   (16 threads/edge, float4 gather,
// 4 scalar atomicAdds -> RED.E.ADD.F32 since the result is unused)
// ---------------------------------------------------------------------------
__global__ void k_scatter(const int* __restrict__ src,
                          const int* __restrict__ dst) {
    long long idx = (long long)blockIdx.x * blockDim.x + threadIdx.x;
    int e = (int)(idx >> 4);
    int c = (int)(idx & 15);
    if (e >= E_EDGES) return;
    int s = src[e];
    int d = dst[e];
    const float4* hv = reinterpret_cast<const float4*>(g_hs + (size_t)s * D);
    float4 v = hv[c];
    float* a = g_agg + (size_t)d * D + c * 4;
    atomicAdd(a + 0, v.x);
    atomicAdd(a + 1, v.y);
    atomicAdd(a + 2, v.z);
    atomicAdd(a + 3, v.w);
}

// ---------------------------------------------------------------------------
// Fused: h1 = tanh(agg * dinv + b1); hs = (h1 @ W2) * dinv; agg = hs
// ---------------------------------------------------------------------------
__global__ void k_layer2(const float* __restrict__ W2, const float* __restrict__ b1) {
    __shared__ float sW[D * D];
    __shared__ float st[4][D];
    int tid = threadIdx.x;
    #pragma unroll
    for (int i = tid; i < D * D; i += 256) sW[i] = W2[i];
    int r = tid >> 6, c = tid & 63;
    int row = blockIdx.x * 4 + r;
    float di = g_dinv[row];
    st[r][c] = tanhf(g_agg[row * D + c] * di + b1[c]);
    __syncthreads();
    float acc = 0.0f;
    #pragma unroll
    for (int k = 0; k < D; k++) acc = fmaf(st[r][k], sW[k * D + c], acc);
    float v = acc * di;
    g_hs [row * D + c] = v;
    g_agg[row * D + c] = v;
}

// ---------------------------------------------------------------------------
// Fused final: h = tanh(agg * dinv + b2)  -> d_out[N*NC ..]  (h output)
//              out = h @ Wc + bc          -> d_out[0 .. N*NC) (logits)
// ---------------------------------------------------------------------------
__global__ void k_final(const float* __restrict__ Wc, const float* __restrict__ b2,
                        const float* __restrict__ bc, float* __restrict__ out) {
    __shared__ float sW[D * NC];
    __shared__ float st[4][D];
    __shared__ float sbc[NC];
    int tid = threadIdx.x;
    #pragma unroll
    for (int i = tid; i < D * NC; i += 256) sW[i] = Wc[i];
    if (tid < NC) sbc[tid] = bc[tid];
    int r = tid >> 6, c = tid & 63;
    int row = blockIdx.x * 4 + r;
    float di = g_dinv[row];
    float h = tanhf(g_agg[row * D + c] * di + b2[c]);
    st[r][c] = h;
    out[(size_t)N_NODES * NC + (size_t)row * D + c] = h;   // h output block
    __syncthreads();
    if (c < NC) {
        float acc = sbc[c];
        #pragma unroll
        for (int k = 0; k < D; k++) acc = fmaf(st[r][k], sW[k * NC + c], acc);
        out[(size_t)row * NC + c] = acc;                   // logits block
    }
}

// ---------------------------------------------------------------------------
extern "C" void kernel_launch(void* const* d_in, const int* in_sizes, int n_in,
                              void* d_out, int out_size) {
    const float* x   = (const float*)d_in[0];
    const int*   ei  = (const int*)d_in[1];   // [2, E] int32 (JAX x64 disabled)
    const float* W1  = (const float*)d_in[2];
    const float* b1  = (const float*)d_in[3];
    const float* W2  = (const float*)d_in[4];
    const float* b2  = (const float*)d_in[5];
    const float* Wc  = (const float*)d_in[6];
    const float* bc  = (const float*)d_in[7];
    float* out = (float*)d_out;

    const int* src = ei;              // edge_index[0]
    const int* dst = ei + E_EDGES;    // edge_index[1]

    const int TB = 256;
    const int gN     = (N_NODES + TB - 1) / TB;
    const int gE     = (E_EDGES + TB - 1) / TB;
    const int gRows  = N_NODES / 4;                       // 12500
    const long long scatterThreads = (long long)E_EDGES * 16;
    const int gScat  = (int)((scatterThreads + TB - 1) / TB);

    k_init_deg  <<<gN, TB>>>();
    k_count_deg <<<gE, TB>>>(dst);
    k_finish_dinv<<<gN, TB>>>();

    k_gemm1   <<<gRows, TB>>>(x, W1);
    k_scatter <<<gScat, TB>>>(src, dst);
    k_layer2  <<<gRows, TB>>>(W2, b1);
    k_scatter <<<gScat, TB>>>(src, dst);
    k_final   <<<gRows, TB>>>(Wc, b2, bc, out);
}

// round 5
// speedup vs baseline: 2.4559x; 2.4559x over previous
#include <cuda_runtime.h>
#include <cuda_bf16.h>

#define N_NODES 50000
#define E_EDGES 800000
#define D 64
#define NC 40
#define RB 64   // rows per block in GEMM kernels

// Scratch (allocation-free rule: __device__ globals). 16B-aligned for float4 access.
__device__ __align__(16) float g_dinv[N_NODES];      // deg, then rsqrt(deg) in place
__device__ __align__(16) float g_hs [N_NODES * D];   // pre-scaled transformed features
__device__ __align__(16) float g_agg[N_NODES * D];   // aggregation target

// ---------------------------------------------------------------------------
// Degree: deg[i] = 1 (self-loop) + #edges with dst==i ; then dinv = rsqrt(deg)
// ---------------------------------------------------------------------------
__global__ void k_init_deg() {
    int i = blockIdx.x * blockDim.x + threadIdx.x;
    if (i < N_NODES) g_dinv[i] = 1.0f;
}

__global__ void k_count_deg(const int* __restrict__ dst) {
    int e = blockIdx.x * blockDim.x + threadIdx.x;
    if (e < E_EDGES) atomicAdd(&g_dinv[dst[e]], 1.0f);
}

__global__ void k_finish_dinv() {
    int i = blockIdx.x * blockDim.x + threadIdx.x;
    if (i < N_NODES) g_dinv[i] = rsqrtf(g_dinv[i]);
}

// ---------------------------------------------------------------------------
// Layer-1 GEMM: hs = (x @ W1) * dinv[row]; agg = hs  (self-loop term)
// 64 rows/block, 256 threads, each thread computes a 4x4 register tile.
// ---------------------------------------------------------------------------
__global__ void k_gemm1(const float* __restrict__ x, const float* __restrict__ W1) {
    __shared__ float sW[D][D];        // sW[k][c]
    __shared__ float sx[RB][D + 1];   // padded: kills bank conflicts on sx[r][k]
    int tid = threadIdx.x;
    int row0 = blockIdx.x * RB;

    // Load W1 (64x64) cooperatively: 16 floats per thread, float4
    #pragma unroll
    for (int i = 0; i < 4; i++) {
        int idx = tid * 4 + i * 1024;            // 256*4 = 1024 floats per pass
        *reinterpret_cast<float4*>(&sW[0][0] + idx) =
            *reinterpret_cast<const float4*>(W1 + idx);
    }
    // Load x tile (64x64): each thread loads 4 float4s
    #pragma unroll
    for (int i = 0; i < 4; i++) {
        int lin = tid + i * 256;                  // element-group index (float4 units)
        int r = lin >> 4;                         // 16 float4 per row
        int c4 = (lin & 15) * 4;
        int row = row0 + r;
        float4 v = make_float4(0.f, 0.f, 0.f, 0.f);
        if (row < N_NODES) v = *reinterpret_cast<const float4*>(x + (size_t)row * D + c4);
        sx[r][c4 + 0] = v.x; sx[r][c4 + 1] = v.y; sx[r][c4 + 2] = v.z; sx[r][c4 + 3] = v.w;
    }
    __syncthreads();

    int tc = tid & 15;          // col group: cols tc*4..tc*4+3
    int tr = tid >> 4;          // row group: rows tr*4..tr*4+3
    float4 acc[4] = {{0,0,0,0},{0,0,0,0},{0,0,0,0},{0,0,0,0}};
    #pragma unroll
    for (int k = 0; k < D; k++) {
        float4 w = *reinterpret_cast<float4*>(&sW[k][tc * 4]);
        #pragma unroll
        for (int i = 0; i < 4; i++) {
            float xv = sx[tr * 4 + i][k];
            acc[i].x = fmaf(xv, w.x, acc[i].x);
            acc[i].y = fmaf(xv, w.y, acc[i].y);
            acc[i].z = fmaf(xv, w.z, acc[i].z);
            acc[i].w = fmaf(xv, w.w, acc[i].w);
        }
    }
    #pragma unroll
    for (int i = 0; i < 4; i++) {
        int row = row0 + tr * 4 + i;
        if (row < N_NODES) {
            float di = g_dinv[row];
            float4 v = make_float4(acc[i].x * di, acc[i].y * di, acc[i].z * di, acc[i].w * di);
            *reinterpret_cast<float4*>(g_hs  + (size_t)row * D + tc * 4) = v;
            *reinterpret_cast<float4*>(g_agg + (size_t)row * D + tc * 4) = v;
        }
    }
}

// ---------------------------------------------------------------------------
// Edge scatter: agg[dst] += hs[src]. 16 threads/edge, one float4 gather +
// one 128-bit vector reduction (sm_90+ atomicAdd(float4*)).
// ---------------------------------------------------------------------------
__global__ void k_scatter(const int* __restrict__ src,
                          const int* __restrict__ dst) {
    long long idx = (long long)blockIdx.x * blockDim.x + threadIdx.x;
    int e = (int)(idx >> 4);
    int c = (int)(idx & 15);
    if (e >= E_EDGES) return;
    int s = src[e];
    int d = dst[e];
    float4 v = reinterpret_cast<const float4*>(g_hs + (size_t)s * D)[c];
    atomicAdd(reinterpret_cast<float4*>(g_agg + (size_t)d * D) + c, v);
}

// ---------------------------------------------------------------------------
// Fused: h1 = tanh(agg * dinv + b1); hs = (h1 @ W2) * dinv; agg = hs
// Same register-blocked structure as k_gemm1.
// ---------------------------------------------------------------------------
__global__ void k_layer2(const float* __restrict__ W2, const float* __restrict__ b1) {
    __shared__ float sW[D][D];
    __shared__ float st[RB][D + 1];
    __shared__ float sb[D];
    int tid = threadIdx.x;
    int row0 = blockIdx.x * RB;

    #pragma unroll
    for (int i = 0; i < 4; i++) {
        int idx = tid * 4 + i * 1024;
        *reinterpret_cast<float4*>(&sW[0][0] + idx) =
            *reinterpret_cast<const float4*>(W2 + idx);
    }
    if (tid < D) sb[tid] = b1[tid];
    __syncthreads();   // sb must be visible before tanh below

    #pragma unroll
    for (int i = 0; i < 4; i++) {
        int lin = tid + i * 256;
        int r = lin >> 4;
        int c4 = (lin & 15) * 4;
        int row = row0 + r;
        float4 v = make_float4(0.f, 0.f, 0.f, 0.f);
        if (row < N_NODES) {
            float di = g_dinv[row];
            float4 a = *reinterpret_cast<const float4*>(g_agg + (size_t)row * D + c4);
            v.x = tanhf(a.x * di + sb[c4 + 0]);
            v.y = tanhf(a.y * di + sb[c4 + 1]);
            v.z = tanhf(a.z * di + sb[c4 + 2]);
            v.w = tanhf(a.w * di + sb[c4 + 3]);
        }
        st[r][c4 + 0] = v.x; st[r][c4 + 1] = v.y; st[r][c4 + 2] = v.z; st[r][c4 + 3] = v.w;
    }
    __syncthreads();

    int tc = tid & 15;
    int tr = tid >> 4;
    float4 acc[4] = {{0,0,0,0},{0,0,0,0},{0,0,0,0},{0,0,0,0}};
    #pragma unroll
    for (int k = 0; k < D; k++) {
        float4 w = *reinterpret_cast<float4*>(&sW[k][tc * 4]);
        #pragma unroll
        for (int i = 0; i < 4; i++) {
            float xv = st[tr * 4 + i][k];
            acc[i].x = fmaf(xv, w.x, acc[i].x);
            acc[i].y = fmaf(xv, w.y, acc[i].y);
            acc[i].z = fmaf(xv, w.z, acc[i].z);
            acc[i].w = fmaf(xv, w.w, acc[i].w);
        }
    }
    #pragma unroll
    for (int i = 0; i < 4; i++) {
        int row = row0 + tr * 4 + i;
        if (row < N_NODES) {
            float di = g_dinv[row];
            float4 v = make_float4(acc[i].x * di, acc[i].y * di, acc[i].z * di, acc[i].w * di);
            *reinterpret_cast<float4*>(g_hs  + (size_t)row * D + tc * 4) = v;
            *reinterpret_cast<float4*>(g_agg + (size_t)row * D + tc * 4) = v;
        }
    }
}

// ---------------------------------------------------------------------------
// Fused final: h = tanh(agg * dinv + b2)  -> d_out[N*NC ..]  (h output)
//              out = h @ Wc + bc          -> d_out[0 .. N*NC) (logits)
// ---------------------------------------------------------------------------
__global__ void k_final(const float* __restrict__ Wc, const float* __restrict__ b2,
                        const float* __restrict__ bc, float* __restrict__ out) {
    __shared__ float sW[D][NC];       // 64 x 40
    __shared__ float st[RB][D + 1];
    __shared__ float sb[D];
    __shared__ float sbc[NC];
    int tid = threadIdx.x;
    int row0 = blockIdx.x * RB;

    // Load Wc (64*40 = 2560 floats = 640 float4)
    #pragma unroll
    for (int i = 0; i < 3; i++) {
        int f4 = tid + i * 256;
        if (f4 < D * NC / 4)
            *(reinterpret_cast<float4*>(&sW[0][0]) + f4) =
                *(reinterpret_cast<const float4*>(Wc) + f4);
    }
    if (tid < D)  sb[tid]  = b2[tid];
    if (tid >= 64 && tid < 64 + NC) sbc[tid - 64] = bc[tid - 64];
    __syncthreads();

    // h = tanh(agg*dinv + b2): compute, write to out's h-block, stage in shared
    #pragma unroll
    for (int i = 0; i < 4; i++) {
        int lin = tid + i * 256;
        int r = lin >> 4;
        int c4 = (lin & 15) * 4;
        int row = row0 + r;
        float4 v = make_float4(0.f, 0.f, 0.f, 0.f);
        if (row < N_NODES) {
            float di = g_dinv[row];
            float4 a = *reinterpret_cast<const float4*>(g_agg + (size_t)row * D + c4);
            v.x = tanhf(a.x * di + sb[c4 + 0]);
            v.y = tanhf(a.y * di + sb[c4 + 1]);
            v.z = tanhf(a.z * di + sb[c4 + 2]);
            v.w = tanhf(a.w * di + sb[c4 + 3]);
            *reinterpret_cast<float4*>(out + (size_t)N_NODES * NC + (size_t)row * D + c4) = v;
        }
        st[r][c4 + 0] = v.x; st[r][c4 + 1] = v.y; st[r][c4 + 2] = v.z; st[r][c4 + 3] = v.w;
    }
    __syncthreads();

    // logits: rows tr*4..+3, cols tc*4..+3 (tc < 10 active)
    int tc = tid & 15;
    int tr = tid >> 4;
    if (tc < NC / 4) {
        float4 acc[4];
        #pragma unroll
        for (int i = 0; i < 4; i++)
            acc[i] = make_float4(sbc[tc*4+0], sbc[tc*4+1], sbc[tc*4+2], sbc[tc*4+3]);
        #pragma unroll
        for (int k = 0; k < D; k++) {
            float4 w = *reinterpret_cast<float4*>(&sW[k][tc * 4]);
            #pragma unroll
            for (int i = 0; i < 4; i++) {
                float xv = st[tr * 4 + i][k];
                acc[i].x = fmaf(xv, w.x, acc[i].x);
                acc[i].y = fmaf(xv, w.y, acc[i].y);
                acc[i].z = fmaf(xv, w.z, acc[i].z);
                acc[i].w = fmaf(xv, w.w, acc[i].w);
            }
        }
        #pragma unroll
        for (int i = 0; i < 4; i++) {
            int row = row0 + tr * 4 + i;
            if (row < N_NODES)
                *reinterpret_cast<float4*>(out + (size_t)row * NC + tc * 4) = acc[i];
        }
    }
}

// ---------------------------------------------------------------------------
extern "C" void kernel_launch(void* const* d_in, const int* in_sizes, int n_in,
                              void* d_out, int out_size) {
    const float* x   = (const float*)d_in[0];
    const int*   ei  = (const int*)d_in[1];   // [2, E] int32 (JAX x64 disabled)
    const float* W1  = (const float*)d_in[2];
    const float* b1  = (const float*)d_in[3];
    const float* W2  = (const float*)d_in[4];
    const float* b2  = (const float*)d_in[5];
    const float* Wc  = (const float*)d_in[6];
    const float* bc  = (const float*)d_in[7];
    float* out = (float*)d_out;

    const int* src = ei;              // edge_index[0]
    const int* dst = ei + E_EDGES;    // edge_index[1]

    const int TB = 256;
    const int gN    = (N_NODES + TB - 1) / TB;
    const int gE    = (E_EDGES + TB - 1) / TB;
    const int gRows = (N_NODES + RB - 1) / RB;            // 782
    const long long scatterThreads = (long long)E_EDGES * 16;
    const int gScat = (int)((scatterThreads + TB - 1) / TB);

    k_init_deg   <<<gN, TB>>>();
    k_count_deg  <<<gE, TB>>>(dst);
    k_finish_dinv<<<gN, TB>>>();

    k_gemm1   <<<gRows, TB>>>(x, W1);
    k_scatter <<<gScat, TB>>>(src, dst);
    k_layer2  <<<gRows, TB>>>(W2, b1);
    k_scatter <<<gScat, TB>>>(src, dst);
    k_final   <<<gRows, TB>>>(Wc, b2, bc, out);
}